// round 13
// baseline (speedup 1.0000x reference)
#include <cuda_runtime.h>

// ---------------- problem constants ----------------
#define Nb   4
#define Cc   15
#define Hh   320
#define Ww   320
#define PADR 11
#define HP   342          // H + 2*PADR
#define NF   32
#define KS   11
#define KR   31
#define IMG  (Hh*Ww)      // 102400
#define NCIMG (Nb*Cc*IMG) // 6144000
#define TABN 2048

typedef unsigned long long ull;

// packed f32x2 helpers (Blackwell)
#define PACKF2(d, lo, hi) asm("mov.b64 %0, {%1, %2};" : "=l"(d) : "f"(lo), "f"(hi))
#define UNPACKF2(lo, hi, v) asm("mov.b64 {%0, %1}, %2;" : "=f"(lo), "=f"(hi) : "l"(v))
#define FMAF2(d, a, b, c) asm("fma.rn.f32x2 %0, %1, %2, %3;" : "=l"(d) : "l"(a), "l"(b), "l"(c))
#define EX2F(d, x) asm("ex2.approx.ftz.f32 %0, %1;" : "=f"(d) : "f"(x))

// ---------------- device scratch ----------------
__device__ float2 d_ws1[NCIMG];
__device__ float2 d_ws2[NCIMG];
__device__ float  d_upad[Nb*2*HP*HP];
__device__ float  d_fuk[Nb*NF*HP*HP];
__device__ float2 d_ru[Nb*IMG];
__device__ float2 d_rbf_tab[NF*TABN];   // (value, delta-to-next) per entry

// ---------------- complex helpers ----------------
__device__ __forceinline__ float2 cadd(float2 a, float2 b){ return make_float2(a.x+b.x, a.y+b.y); }
__device__ __forceinline__ float2 csub(float2 a, float2 b){ return make_float2(a.x-b.x, a.y-b.y); }
__device__ __forceinline__ float2 cmul(float2 a, float2 b){ return make_float2(a.x*b.x-a.y*b.y, a.x*b.y+a.y*b.x); }

// ---------- 320-point in-place Stockham FFT (radix 4,4,4,5), 16 thr/line ----------
#define LINES 8
#define SMW   321

template<int NS>
__device__ __forceinline__ void r4ip(float2* A, int t, float dir){
  float2 v[5][4];
#pragma unroll
  for (int it = 0; it < 5; ++it){
    int j = t + (it << 4);
    v[it][0] = A[j]; v[it][1] = A[j+80]; v[it][2] = A[j+160]; v[it][3] = A[j+240];
  }
  __syncthreads();
#pragma unroll
  for (int it = 0; it < 5; ++it){
    int j    = t + (it << 4);
    int base = j & (NS - 1);
    int grp  = j / NS;
    float2 v0 = v[it][0], v1 = v[it][1], v2 = v[it][2], v3 = v[it][3];
    if (NS > 1){
      float ang = dir * (6.2831853071795864f / (4.0f*NS)) * (float)base;
      float s, c; __sincosf(ang, &s, &c);
      float2 w1 = make_float2(c, s);
      float2 w2 = cmul(w1, w1);
      float2 w3 = cmul(w2, w1);
      v1 = cmul(v1, w1); v2 = cmul(v2, w2); v3 = cmul(v3, w3);
    }
    float2 a0 = cadd(v0, v2), a1 = csub(v0, v2);
    float2 a2 = cadd(v1, v3), a3 = csub(v1, v3);
    float2 ja3 = make_float2(-dir*a3.y, dir*a3.x);
    int o = grp*(NS*4) + base;
    A[o]      = cadd(a0, a2);
    A[o+NS]   = cadd(a1, ja3);
    A[o+2*NS] = csub(a0, a2);
    A[o+3*NS] = csub(a1, ja3);
  }
  __syncthreads();
}

__device__ __forceinline__ void r5ip(float2* A, int t, float dir){
  const float C1 = 0.30901699437494745f, S1 = 0.9510565162951535f;
  const float C2 = -0.8090169943749473f, S2 = 0.5877852522924731f;
  float2 v[4][5];
#pragma unroll
  for (int it = 0; it < 4; ++it){
    int j = t + (it << 4);
    v[it][0]=A[j]; v[it][1]=A[j+64]; v[it][2]=A[j+128]; v[it][3]=A[j+192]; v[it][4]=A[j+256];
  }
  __syncthreads();
#pragma unroll
  for (int it = 0; it < 4; ++it){
    int j = t + (it << 4);
    float2 v0=v[it][0], v1=v[it][1], v2=v[it][2], v3=v[it][3], v4=v[it][4];
    float ang = dir * (6.2831853071795864f / 320.0f) * (float)j;
    float s, c; __sincosf(ang, &s, &c);
    float2 w1 = make_float2(c, s);
    float2 w2 = cmul(w1, w1);
    float2 w3 = cmul(w2, w1);
    float2 w4 = cmul(w2, w2);
    v1 = cmul(v1, w1); v2 = cmul(v2, w2); v3 = cmul(v3, w3); v4 = cmul(v4, w4);
    float2 t1 = cadd(v1, v4), t2 = cadd(v2, v3);
    float2 t3 = csub(v1, v4), t4 = csub(v2, v3);
    float2 X0 = cadd(v0, cadd(t1, t2));
    float2 m1 = make_float2(v0.x + C1*t1.x + C2*t2.x, v0.y + C1*t1.y + C2*t2.y);
    float2 m2 = make_float2(v0.x + C2*t1.x + C1*t2.x, v0.y + C2*t1.y + C1*t2.y);
    float2 s3 = make_float2(S1*t3.x + S2*t4.x, S1*t3.y + S2*t4.y);
    float2 s4 = make_float2(S2*t3.x - S1*t4.x, S2*t3.y - S1*t4.y);
    float2 js3 = make_float2(-dir*s3.y, dir*s3.x);
    float2 js4 = make_float2(-dir*s4.y, dir*s4.x);
    A[j]     = X0;
    A[j+64]  = cadd(m1, js3);
    A[j+128] = cadd(m2, js4);
    A[j+192] = csub(m2, js4);
    A[j+256] = csub(m1, js3);
  }
  __syncthreads();
}

__device__ __forceinline__ void fft320ip(float2* A, int t, float dir){
  r4ip<1>(A, t, dir);
  r4ip<4>(A, t, dir);
  r4ip<16>(A, t, dir);
  r5ip(A, t, dir);
}

// Pass A: sgn*u*coil -> row FFT (fwd) -> ws1
__global__ void __launch_bounds__(128, 8) k_dcA(const float* __restrict__ u, const float* __restrict__ coil){
  __shared__ float2 sA[LINES*SMW];
  int tid = threadIdx.x;
  int img = blockIdx.x / 40;
  int r0  = (blockIdx.x % 40) * 8;
  int n   = img / Cc;
  const float2* up = (const float2*)u + (long)n*IMG;
  const float2* cp = (const float2*)coil + (long)img*IMG;
  for (int idx = tid; idx < LINES*320; idx += 128){
    int l = idx / 320, p = idx - l*320;
    int r = r0 + l;
    float2 uv = up[(long)r*Ww + p];
    float2 cv = cp[(long)r*Ww + p];
    float sgn = ((r + p) & 1) ? -1.f : 1.f;
    sA[l*SMW + p] = make_float2(sgn*(uv.x*cv.x - uv.y*cv.y), sgn*(uv.x*cv.y + uv.y*cv.x));
  }
  __syncthreads();
  fft320ip(sA + (tid >> 4)*SMW, tid & 15, -1.f);
  float2* dp = d_ws1 + (long)img*IMG + (long)r0*Ww;
  for (int idx = tid; idx < LINES*320; idx += 128){
    int l = idx / 320, p = idx - l*320;
    dp[idx] = sA[l*SMW + p];
  }
}

// Pass B: col FFT fwd -> mask*(v/320 - sgn*f) -> col FFT inv -> ws2
__global__ void __launch_bounds__(128, 8) k_dcB(const float* __restrict__ f, const float* __restrict__ mask){
  __shared__ float2 sA[LINES*SMW];
  int tid = threadIdx.x;
  int img = blockIdx.x / 40;
  int c0  = (blockIdx.x % 40) * 8;
  int n   = img / Cc;
  const float2* sp = d_ws1 + (long)img*IMG + c0;
  for (int idx = tid; idx < LINES*320; idx += 128){
    int r = idx >> 3, cc = idx & 7;
    sA[cc*SMW + r] = sp[(long)r*Ww + cc];
  }
  __syncthreads();
  fft320ip(sA + (tid >> 4)*SMW, tid & 15, -1.f);
  const float2* fp = (const float2*)f + (long)img*IMG + c0;
  const float*  mp = mask + (long)n*IMG + c0;
  for (int idx = tid; idx < LINES*320; idx += 128){
    int r = idx >> 3, cc = idx & 7;
    float2 v = sA[cc*SMW + r];
    float2 fv = fp[(long)r*Ww + cc];
    float  mv = mp[(long)r*Ww + cc];
    float sgn = ((r + c0 + cc) & 1) ? -1.f : 1.f;
    v.x = mv*(v.x*(1.f/320.f) - sgn*fv.x);
    v.y = mv*(v.y*(1.f/320.f) - sgn*fv.y);
    sA[cc*SMW + r] = v;
  }
  __syncthreads();
  fft320ip(sA + (tid >> 4)*SMW, tid & 15, 1.f);
  float2* dp = d_ws2 + (long)img*IMG + c0;
  for (int idx = tid; idx < LINES*320; idx += 128){
    int r = idx >> 3, cc = idx & 7;
    dp[(long)r*Ww + cc] = sA[cc*SMW + r];
  }
}

// Pass C fused with final combine:
// block = (n, row). 16 lines: 15 coils' row r of ws2 + 1 dummy.
// row inverse FFT -> out = u - Ru - lamb*sgn*(1/320)*sum_c V_c*conj(coil_c)
__global__ void __launch_bounds__(256) k_dcC(const float* __restrict__ u,
                                             const float* __restrict__ coil,
                                             const float* __restrict__ lamb,
                                             float2* __restrict__ out){
  __shared__ float2 sA[16*SMW];
  int tid = threadIdx.x;
  int n = blockIdx.x / Hh;
  int r = blockIdx.x - n*Hh;
  for (int idx = tid; idx < 16*320; idx += 256){
    int line = idx / 320;
    int p = idx - line*320;
    float2 v = make_float2(0.f, 0.f);
    if (line < Cc)
      v = d_ws2[((long)(n*Cc + line))*IMG + (long)r*Ww + p];
    sA[line*SMW + p] = v;
  }
  __syncthreads();
  fft320ip(sA + (tid >> 4)*SMW, tid & 15, 1.f);
  float lam = lamb[0];
  for (int p = tid; p < 320; p += 256){
    float ax = 0.f, ay = 0.f;
#pragma unroll 1
    for (int c = 0; c < Cc; ++c){
      float2 wv = sA[c*SMW + p];
      float2 cc = ((const float2*)coil)[((long)(n*Cc + c))*IMG + (long)r*Ww + p];
      ax += wv.x*cc.x + wv.y*cc.y;
      ay += wv.y*cc.x - wv.x*cc.y;
    }
    float sgn = ((r + p) & 1) ? -1.f : 1.f;
    float s = lam * sgn * (1.f/320.f);
    long q = (long)n*IMG + (long)r*Ww + p;
    float2 uv = ((const float2*)u)[q];
    float2 rv = d_ru[q];
    out[q] = make_float2(uv.x - rv.x - s*ax, uv.y - rv.y - s*ay);
  }
}

// ---------------- regularizer path ----------------
__global__ void k_pad(const float* __restrict__ u){
  int idx = blockIdx.x*256 + threadIdx.x;
  const int total = Nb*2*HP*HP;
  if (idx >= total) return;
  int xx = idx % HP; int t1 = idx / HP;
  int yy = t1 % HP;  int t2 = t1 / HP;
  int comp = t2 & 1; int n = t2 >> 1;
  int p = yy - PADR; if (p < 0) p = -p; else if (p >= Hh) p = 2*Hh - 2 - p;
  int q = xx - PADR; if (q < 0) q = -q; else if (q >= Ww) q = 2*Ww - 2 - q;
  d_upad[idx] = u[(((long)n*Hh + p)*Ww + q)*2 + comp];
}

// Build per-feature RBF lookup table: 2048 entries over [-2,2], (value, delta) for lerp.
__global__ void k_rbf_build(const float* __restrict__ wrbf, const float* __restrict__ mu,
                            const float* __restrict__ sigma){
  int fo = blockIdx.x;
  float sg = sigma[0];
  float inv2s2 = 0.5f/(sg*sg);
  float mu0 = mu[0];
  float dmu = mu[1] - mu0;
  const float lo = -2.f, h = 4.f/(float)(TABN - 1);
  float wloc[KR];
#pragma unroll 1
  for (int k = 0; k < KR; ++k) wloc[k] = wrbf[fo*KR + k];
  for (int j = threadIdx.x; j < TABN; j += 256){
    float u0 = lo + h*(float)j;
    float u1 = u0 + h;
    float s0 = 0.f, s1 = 0.f;
#pragma unroll 1
    for (int k = 0; k < KR; ++k){
      float m = fmaf((float)k, dmu, mu0);
      float d0 = u0 - m, d1 = u1 - m;
      s0 += wloc[k] * __expf(-d0*d0*inv2s2);
      s1 += wloc[k] * __expf(-d1*d1*inv2s2);
    }
    d_rbf_tab[fo*TABN + j] = make_float2(s0, s1 - s0);
  }
}

// conv(2->32, 11x11, pad 5) fused with LUT-RBF activation -> d_fuk
// block 16x16 threads, tile 64x16 px, 16 output feats per block (z parity)
__global__ void __launch_bounds__(256, 2) k_conv_rbf(const float* __restrict__ ck){
  __shared__ float4 sW[16*121];     // (wx,wx,wy,wy)
  __shared__ float  sIn[2*26*74];
  int tx = threadIdx.x, ty = threadIdx.y;
  int tid = ty*16 + tx;
  int z = blockIdx.z, n = z >> 1, fo0 = (z & 1)*16;
  for (int i = tid; i < 16*121; i += 256){
    int fo = i/121, tap = i - fo*121;
    float2 w = ((const float2*)ck)[(fo0+fo)*121 + tap];
    sW[i] = make_float4(w.x, w.x, w.y, w.y);
  }
  int y0 = blockIdx.y*16, x0 = blockIdx.x*64;
  for (int i = tid; i < 2*26*74; i += 256){
    int comp = i / (26*74), rem = i - comp*(26*74);
    int iy = rem/74, ix = rem - iy*74;
    int gy = y0 - 5 + iy, gx = x0 - 5 + ix;
    float v = 0.f;
    if (gy >= 0 && gy < HP && gx >= 0 && gx < HP)
      v = d_upad[((long)(n*2+comp)*HP + gy)*HP + gx];
    sIn[i] = v;
  }
  __syncthreads();

  ull acc[32];
#pragma unroll
  for (int i = 0; i < 32; ++i) acc[i] = 0ull;

  for (int ky = 0; ky < 11; ++ky){
#pragma unroll
    for (int kx = 0; kx < 11; ++kx){
      int ro = (ty+ky)*74 + tx + kx;
      float r0a = sIn[ro],      r0b = sIn[ro+16];
      float r1a = sIn[ro+32],   r1b = sIn[ro+48];
      float q0a = sIn[1924+ro],    q0b = sIn[1924+ro+16];
      float q1a = sIn[1924+ro+32], q1b = sIn[1924+ro+48];
      ull vr0, vr1, vi0, vi1;
      PACKF2(vr0, r0a, r0b); PACKF2(vr1, r1a, r1b);
      PACKF2(vi0, q0a, q0b); PACKF2(vi1, q1a, q1b);
      const ulonglong2* wp = reinterpret_cast<const ulonglong2*>(sW) + (ky*11 + kx);
#pragma unroll
      for (int fo = 0; fo < 16; ++fo){
        ulonglong2 w = wp[fo*121];
        FMAF2(acc[2*fo],   vr0, w.x, acc[2*fo]);
        FMAF2(acc[2*fo],   vi0, w.y, acc[2*fo]);
        FMAF2(acc[2*fo+1], vr1, w.x, acc[2*fo+1]);
        FMAF2(acc[2*fo+1], vi1, w.y, acc[2*fo+1]);
      }
    }
  }

  // LUT-RBF epilogue: clamp, scale, gather (value,delta), lerp
  const float lo = -2.f;
  const float invh = (float)(TABN - 1) / 4.f;
  int ybase = y0 + ty;
  bool yok = (ybase < HP);
  long obase = ((long)(n*NF + fo0)*HP + ybase)*HP + x0 + tx;
#pragma unroll 1
  for (int fo = 0; fo < 16; ++fo){
    const float2* tab = d_rbf_tab + (fo0 + fo)*TABN;
#pragma unroll
    for (int pr = 0; pr < 2; ++pr){
      float ulo, uhi;
      UNPACKF2(ulo, uhi, acc[2*fo+pr]);
#pragma unroll
      for (int hf = 0; hf < 2; ++hf){
        float uv = hf ? uhi : ulo;
        int xoff = pr*32 + hf*16;
        int gx = x0 + tx + xoff;
        if (yok && gx < HP){
          float t = (uv - lo) * invh;
          t = fminf(fmaxf(t, 0.f), (float)(TABN - 1) - 1.001f);
          int i = (int)t;
          float fr = t - (float)i;
          float2 e = __ldg(&tab[i]);
          d_fuk[obase + (long)fo*HP*HP + xoff] = fmaf(e.y, fr, e.x);
        }
      }
    }
  }
}

// transposed conv (32->2), inner 320x320, /32
// block (8,32), tile 64x32 px, 8 px per thread, 32 channels/block,
// double-buffered channel staging + all-weights preload (1 sync/channel)
__global__ void __launch_bounds__(256) k_convT(const float* __restrict__ ck){
  __shared__ float  sIn[2][42*76];     // 2 x 12.8 KB
  __shared__ float2 sWall[NF*121];     // 30.25 KB
  int tx = threadIdx.x;    // 0..7
  int ty = threadIdx.y;    // 0..31
  int tid = ty*8 + tx;
  int n = blockIdx.z;
  int y0 = blockIdx.y*32, x0 = blockIdx.x*64;

  // preload ALL channel weights once
  for (int i = tid; i < NF*121; i += 256)
    sWall[i] = ((const float2*)ck)[i];

  // preload channel 0 into buffer 0
  {
    const float* src = d_fuk + (((long)(n*NF))*HP + (y0 + 6))*HP + (x0 + 6);
    for (int i = tid; i < 42*74; i += 256){
      int iy = i/74, ix = i - iy*74;
      sIn[0][iy*76 + ix] = src[(long)iy*HP + ix];
    }
  }
  __syncthreads();

  ull acc[8];
#pragma unroll
  for (int i = 0; i < 8; ++i) acc[i] = 0ull;

#pragma unroll 1
  for (int ch = 0; ch < NF; ++ch){
    int cur = ch & 1;
    // prefetch next channel into the other buffer (overlaps with compute below)
    if (ch + 1 < NF){
      const float* src = d_fuk + (((long)(n*NF + ch + 1))*HP + (y0 + 6))*HP + (x0 + 6);
      for (int i = tid; i < 42*74; i += 256){
        int iy = i/74, ix = i - iy*74;
        sIn[cur ^ 1][iy*76 + ix] = src[(long)iy*HP + ix];
      }
    }
    const ull* wch = reinterpret_cast<const ull*>(sWall) + ch*121;
    const float* buf = sIn[cur];
    for (int ly = 0; ly < 11; ++ly){
      const float* row = buf + (ty + 10 - ly)*76 + tx*8;
      float4 va = *(const float4*)(row);
      float4 vb = *(const float4*)(row + 4);
      float4 vc = *(const float4*)(row + 8);
      float4 vd = *(const float4*)(row + 12);
      float4 ve = *(const float4*)(row + 16);
      float vv[18] = {va.x,va.y,va.z,va.w, vb.x,vb.y,vb.z,vb.w,
                      vc.x,vc.y,vc.z,vc.w, vd.x,vd.y,vd.z,vd.w,
                      ve.x,ve.y};
      ull vdup[18];
#pragma unroll
      for (int j = 0; j < 18; ++j) PACKF2(vdup[j], vv[j], vv[j]);
#pragma unroll
      for (int lx = 0; lx < 11; ++lx){
        ull wp = wch[ly*11 + lx];          // (wx, wy)
#pragma unroll
        for (int p = 0; p < 8; ++p){
          FMAF2(acc[p], vdup[p + 10 - lx], wp, acc[p]);
        }
      }
    }
    __syncthreads();
  }
  float sc = 1.0f/NF;
#pragma unroll
  for (int p = 0; p < 8; ++p){
    float ax, ay; UNPACKF2(ax, ay, acc[p]);
    d_ru[((long)n*Hh + (y0 + ty))*Ww + (x0 + tx*8 + p)] = make_float2(ax*sc, ay*sc);
  }
}

// ---------------- launcher ----------------
extern "C" void kernel_launch(void* const* d_in, const int* in_sizes, int n_in,
                              void* d_out, int out_size){
  const float* u     = (const float*)d_in[0];
  const float* f     = (const float*)d_in[1];
  const float* coil  = (const float*)d_in[2];
  const float* mask  = (const float*)d_in[3];
  const float* ck    = (const float*)d_in[4];
  const float* wrbf  = (const float*)d_in[5];
  const float* mu    = (const float*)d_in[6];
  const float* sigma = (const float*)d_in[7];
  const float* lamb  = (const float*)d_in[8];
  float2* out = (float2*)d_out;

  // regularizer path
  k_rbf_build<<<NF, 256>>>(wrbf, mu, sigma);
  k_pad<<<(Nb*2*HP*HP + 255)/256, 256>>>(u);
  k_conv_rbf<<<dim3(6, 22, 8), dim3(16, 16)>>>(ck);
  k_convT<<<dim3(5, 10, 4), dim3(8, 32)>>>(ck);

  // data-consistency path (fused)
  k_dcA<<<Nb*Cc*40, 128>>>(u, coil);
  k_dcB<<<Nb*Cc*40, 128>>>(f, mask);
  k_dcC<<<Nb*Hh, 256>>>(u, coil, lamb, out);
}

// round 14
// speedup vs baseline: 1.0876x; 1.0876x over previous
#include <cuda_runtime.h>

// ---------------- problem constants ----------------
#define Nb   4
#define Cc   15
#define Hh   320
#define Ww   320
#define PADR 11
#define HP   342          // H + 2*PADR
#define NF   32
#define KS   11
#define KR   31
#define IMG  (Hh*Ww)      // 102400
#define NCIMG (Nb*Cc*IMG) // 6144000
#define TABN 2048

typedef unsigned long long ull;

// packed f32x2 helpers (Blackwell)
#define PACKF2(d, lo, hi) asm("mov.b64 %0, {%1, %2};" : "=l"(d) : "f"(lo), "f"(hi))
#define UNPACKF2(lo, hi, v) asm("mov.b64 {%0, %1}, %2;" : "=f"(lo), "=f"(hi) : "l"(v))
#define FMAF2(d, a, b, c) asm("fma.rn.f32x2 %0, %1, %2, %3;" : "=l"(d) : "l"(a), "l"(b), "l"(c))
#define EX2F(d, x) asm("ex2.approx.ftz.f32 %0, %1;" : "=f"(d) : "f"(x))

// ---------------- device scratch ----------------
__device__ float2 d_ws1[NCIMG];
__device__ float2 d_ws2[NCIMG];
__device__ float  d_upad[Nb*2*HP*HP];
__device__ float  d_fuk[Nb*NF*HP*HP];
__device__ float2 d_ru[Nb*IMG];
__device__ float2 d_ru2[Nb*IMG];
__device__ float2 d_rbf_tab[NF*TABN];   // (value, delta-to-next) per entry

// ---------------- complex helpers ----------------
__device__ __forceinline__ float2 cadd(float2 a, float2 b){ return make_float2(a.x+b.x, a.y+b.y); }
__device__ __forceinline__ float2 csub(float2 a, float2 b){ return make_float2(a.x-b.x, a.y-b.y); }
__device__ __forceinline__ float2 cmul(float2 a, float2 b){ return make_float2(a.x*b.x-a.y*b.y, a.x*b.y+a.y*b.x); }

// ---------- 320-point in-place Stockham FFT (radix 4,4,4,5), 16 thr/line ----------
#define LINES 8
#define SMW   321

template<int NS>
__device__ __forceinline__ void r4ip(float2* A, int t, float dir){
  float2 v[5][4];
#pragma unroll
  for (int it = 0; it < 5; ++it){
    int j = t + (it << 4);
    v[it][0] = A[j]; v[it][1] = A[j+80]; v[it][2] = A[j+160]; v[it][3] = A[j+240];
  }
  __syncthreads();
#pragma unroll
  for (int it = 0; it < 5; ++it){
    int j    = t + (it << 4);
    int base = j & (NS - 1);
    int grp  = j / NS;
    float2 v0 = v[it][0], v1 = v[it][1], v2 = v[it][2], v3 = v[it][3];
    if (NS > 1){
      float ang = dir * (6.2831853071795864f / (4.0f*NS)) * (float)base;
      float s, c; __sincosf(ang, &s, &c);
      float2 w1 = make_float2(c, s);
      float2 w2 = cmul(w1, w1);
      float2 w3 = cmul(w2, w1);
      v1 = cmul(v1, w1); v2 = cmul(v2, w2); v3 = cmul(v3, w3);
    }
    float2 a0 = cadd(v0, v2), a1 = csub(v0, v2);
    float2 a2 = cadd(v1, v3), a3 = csub(v1, v3);
    float2 ja3 = make_float2(-dir*a3.y, dir*a3.x);
    int o = grp*(NS*4) + base;
    A[o]      = cadd(a0, a2);
    A[o+NS]   = cadd(a1, ja3);
    A[o+2*NS] = csub(a0, a2);
    A[o+3*NS] = csub(a1, ja3);
  }
  __syncthreads();
}

__device__ __forceinline__ void r5ip(float2* A, int t, float dir){
  const float C1 = 0.30901699437494745f, S1 = 0.9510565162951535f;
  const float C2 = -0.8090169943749473f, S2 = 0.5877852522924731f;
  float2 v[4][5];
#pragma unroll
  for (int it = 0; it < 4; ++it){
    int j = t + (it << 4);
    v[it][0]=A[j]; v[it][1]=A[j+64]; v[it][2]=A[j+128]; v[it][3]=A[j+192]; v[it][4]=A[j+256];
  }
  __syncthreads();
#pragma unroll
  for (int it = 0; it < 4; ++it){
    int j = t + (it << 4);
    float2 v0=v[it][0], v1=v[it][1], v2=v[it][2], v3=v[it][3], v4=v[it][4];
    float ang = dir * (6.2831853071795864f / 320.0f) * (float)j;
    float s, c; __sincosf(ang, &s, &c);
    float2 w1 = make_float2(c, s);
    float2 w2 = cmul(w1, w1);
    float2 w3 = cmul(w2, w1);
    float2 w4 = cmul(w2, w2);
    v1 = cmul(v1, w1); v2 = cmul(v2, w2); v3 = cmul(v3, w3); v4 = cmul(v4, w4);
    float2 t1 = cadd(v1, v4), t2 = cadd(v2, v3);
    float2 t3 = csub(v1, v4), t4 = csub(v2, v3);
    float2 X0 = cadd(v0, cadd(t1, t2));
    float2 m1 = make_float2(v0.x + C1*t1.x + C2*t2.x, v0.y + C1*t1.y + C2*t2.y);
    float2 m2 = make_float2(v0.x + C2*t1.x + C1*t2.x, v0.y + C2*t1.y + C1*t2.y);
    float2 s3 = make_float2(S1*t3.x + S2*t4.x, S1*t3.y + S2*t4.y);
    float2 s4 = make_float2(S2*t3.x - S1*t4.x, S2*t3.y - S1*t4.y);
    float2 js3 = make_float2(-dir*s3.y, dir*s3.x);
    float2 js4 = make_float2(-dir*s4.y, dir*s4.x);
    A[j]     = X0;
    A[j+64]  = cadd(m1, js3);
    A[j+128] = cadd(m2, js4);
    A[j+192] = csub(m2, js4);
    A[j+256] = csub(m1, js3);
  }
  __syncthreads();
}

__device__ __forceinline__ void fft320ip(float2* A, int t, float dir){
  r4ip<1>(A, t, dir);
  r4ip<4>(A, t, dir);
  r4ip<16>(A, t, dir);
  r5ip(A, t, dir);
}

// ---------------- merged kernel: convT blocks (0..399) + dcA 16-line blocks (400..1599) ----------------
#define CT_BLOCKS 400

__global__ void __launch_bounds__(256, 4) k_mix(const float* __restrict__ ck,
                                                const float* __restrict__ u,
                                                const float* __restrict__ coil){
  __shared__ __align__(16) char smraw[41088];
  int b = blockIdx.x;
  int tid = threadIdx.x;

  if (b < CT_BLOCKS){
    // ---- transposed conv (32->2), z-split halves of 16 channels ----
    float*  sIn0 = (float*)smraw;                 // 42*76
    float*  sIn1 = sIn0 + 42*76;                  // 42*76
    float2* sW16 = (float2*)(sIn0 + 2*42*76);     // 16*121 float2
    int tx = tid & 7;
    int ty = tid >> 3;
    int bx = b % 5; int t1 = b / 5;
    int by = t1 % 10; int z = t1 / 10;
    int n = z >> 1;
    int cbase = (z & 1)*16;
    int y0 = by*32, x0 = bx*64;

    // preload all 16 channel weights once
    for (int i = tid; i < 16*121; i += 256)
      sW16[i] = ((const float2*)ck)[(cbase + i/121)*121 + (i % 121)];

    ull acc[8];
#pragma unroll
    for (int i = 0; i < 8; ++i) acc[i] = 0ull;

#pragma unroll 1
    for (int cp = 0; cp < 8; ++cp){
      __syncthreads();
      // stage 2 channels (one barrier pair per 2 channels)
      for (int i = tid; i < 2*42*74; i += 256){
        int ch = i / (42*74); int rem = i - ch*(42*74);
        int iy = rem/74, ix = rem - iy*74;
        const float* src = d_fuk + (((long)(n*NF + cbase + cp*2 + ch))*HP + (y0 + 6))*HP + (x0 + 6);
        float* dst = ch ? sIn1 : sIn0;
        dst[iy*76 + ix] = src[(long)iy*HP + ix];
      }
      __syncthreads();
#pragma unroll 1
      for (int ch = 0; ch < 2; ++ch){
        const ull* wch = reinterpret_cast<const ull*>(sW16) + (cp*2 + ch)*121;
        const float* buf = ch ? sIn1 : sIn0;
        for (int ly = 0; ly < 11; ++ly){
          const float* row = buf + (ty + 10 - ly)*76 + tx*8;
          float4 va = *(const float4*)(row);
          float4 vb = *(const float4*)(row + 4);
          float4 vc = *(const float4*)(row + 8);
          float4 vd = *(const float4*)(row + 12);
          float4 ve = *(const float4*)(row + 16);
          float vv[18] = {va.x,va.y,va.z,va.w, vb.x,vb.y,vb.z,vb.w,
                          vc.x,vc.y,vc.z,vc.w, vd.x,vd.y,vd.z,vd.w,
                          ve.x,ve.y};
          ull vdup[18];
#pragma unroll
          for (int j = 0; j < 18; ++j) PACKF2(vdup[j], vv[j], vv[j]);
#pragma unroll
          for (int lx = 0; lx < 11; ++lx){
            ull wp = wch[ly*11 + lx];          // (wx, wy)
#pragma unroll
            for (int p = 0; p < 8; ++p){
              FMAF2(acc[p], vdup[p + 10 - lx], wp, acc[p]);
            }
          }
        }
      }
    }
    float sc = 1.0f/NF;
    float2* dst = (z & 1) ? d_ru2 : d_ru;
#pragma unroll
    for (int p = 0; p < 8; ++p){
      float ax, ay; UNPACKF2(ax, ay, acc[p]);
      dst[((long)n*Hh + (y0 + ty))*Ww + (x0 + tx*8 + p)] = make_float2(ax*sc, ay*sc);
    }
  } else {
    // ---- dcA: sgn*u*coil -> row FFT (fwd) -> ws1, 16 lines per block ----
    float2* sA = (float2*)smraw;   // 16*SMW
    int bb = b - CT_BLOCKS;
    int img = bb / 20;
    int r0  = (bb % 20) * 16;
    int n   = img / Cc;
    const float2* up = (const float2*)u + (long)n*IMG;
    const float2* cp = (const float2*)coil + (long)img*IMG;
    for (int idx = tid; idx < 16*320; idx += 256){
      int l = idx / 320, p = idx - l*320;
      int r = r0 + l;
      float2 uv = up[(long)r*Ww + p];
      float2 cv = cp[(long)r*Ww + p];
      float sgn = ((r + p) & 1) ? -1.f : 1.f;
      sA[l*SMW + p] = make_float2(sgn*(uv.x*cv.x - uv.y*cv.y), sgn*(uv.x*cv.y + uv.y*cv.x));
    }
    __syncthreads();
    fft320ip(sA + (tid >> 4)*SMW, tid & 15, -1.f);
    float2* dp = d_ws1 + (long)img*IMG + (long)r0*Ww;
    for (int idx = tid; idx < 16*320; idx += 256){
      int l = idx / 320, p = idx - l*320;
      dp[idx] = sA[l*SMW + p];
    }
  }
}

// Pass B: col FFT fwd -> mask*(v/320 - sgn*f) -> col FFT inv -> ws2
__global__ void __launch_bounds__(128, 8) k_dcB(const float* __restrict__ f, const float* __restrict__ mask){
  __shared__ float2 sA[LINES*SMW];
  int tid = threadIdx.x;
  int img = blockIdx.x / 40;
  int c0  = (blockIdx.x % 40) * 8;
  int n   = img / Cc;
  const float2* sp = d_ws1 + (long)img*IMG + c0;
  for (int idx = tid; idx < LINES*320; idx += 128){
    int r = idx >> 3, cc = idx & 7;
    sA[cc*SMW + r] = sp[(long)r*Ww + cc];
  }
  __syncthreads();
  fft320ip(sA + (tid >> 4)*SMW, tid & 15, -1.f);
  const float2* fp = (const float2*)f + (long)img*IMG + c0;
  const float*  mp = mask + (long)n*IMG + c0;
  for (int idx = tid; idx < LINES*320; idx += 128){
    int r = idx >> 3, cc = idx & 7;
    float2 v = sA[cc*SMW + r];
    float2 fv = fp[(long)r*Ww + cc];
    float  mv = mp[(long)r*Ww + cc];
    float sgn = ((r + c0 + cc) & 1) ? -1.f : 1.f;
    v.x = mv*(v.x*(1.f/320.f) - sgn*fv.x);
    v.y = mv*(v.y*(1.f/320.f) - sgn*fv.y);
    sA[cc*SMW + r] = v;
  }
  __syncthreads();
  fft320ip(sA + (tid >> 4)*SMW, tid & 15, 1.f);
  float2* dp = d_ws2 + (long)img*IMG + c0;
  for (int idx = tid; idx < LINES*320; idx += 128){
    int r = idx >> 3, cc = idx & 7;
    dp[(long)r*Ww + cc] = sA[cc*SMW + r];
  }
}

// Pass C fused with final combine:
// block = (n, row). 16 lines: 15 coils' row r of ws2 + 1 dummy.
// row inverse FFT -> out = u - Ru - Ru2 - lamb*sgn*(1/320)*sum_c V_c*conj(coil_c)
__global__ void __launch_bounds__(256) k_dcC(const float* __restrict__ u,
                                             const float* __restrict__ coil,
                                             const float* __restrict__ lamb,
                                             float2* __restrict__ out){
  __shared__ float2 sA[16*SMW];
  int tid = threadIdx.x;
  int n = blockIdx.x / Hh;
  int r = blockIdx.x - n*Hh;
  for (int idx = tid; idx < 16*320; idx += 256){
    int line = idx / 320;
    int p = idx - line*320;
    float2 v = make_float2(0.f, 0.f);
    if (line < Cc)
      v = d_ws2[((long)(n*Cc + line))*IMG + (long)r*Ww + p];
    sA[line*SMW + p] = v;
  }
  __syncthreads();
  fft320ip(sA + (tid >> 4)*SMW, tid & 15, 1.f);
  float lam = lamb[0];
  for (int p = tid; p < 320; p += 256){
    float ax = 0.f, ay = 0.f;
#pragma unroll 1
    for (int c = 0; c < Cc; ++c){
      float2 wv = sA[c*SMW + p];
      float2 cc = ((const float2*)coil)[((long)(n*Cc + c))*IMG + (long)r*Ww + p];
      ax += wv.x*cc.x + wv.y*cc.y;
      ay += wv.y*cc.x - wv.x*cc.y;
    }
    float sgn = ((r + p) & 1) ? -1.f : 1.f;
    float s = lam * sgn * (1.f/320.f);
    long q = (long)n*IMG + (long)r*Ww + p;
    float2 uv = ((const float2*)u)[q];
    float2 rv = d_ru[q];
    float2 rv2 = d_ru2[q];
    out[q] = make_float2(uv.x - rv.x - rv2.x - s*ax, uv.y - rv.y - rv2.y - s*ay);
  }
}

// ---------------- regularizer path ----------------
__global__ void k_pad(const float* __restrict__ u){
  int idx = blockIdx.x*256 + threadIdx.x;
  const int total = Nb*2*HP*HP;
  if (idx >= total) return;
  int xx = idx % HP; int t1 = idx / HP;
  int yy = t1 % HP;  int t2 = t1 / HP;
  int comp = t2 & 1; int n = t2 >> 1;
  int p = yy - PADR; if (p < 0) p = -p; else if (p >= Hh) p = 2*Hh - 2 - p;
  int q = xx - PADR; if (q < 0) q = -q; else if (q >= Ww) q = 2*Ww - 2 - q;
  d_upad[idx] = u[(((long)n*Hh + p)*Ww + q)*2 + comp];
}

// Build per-feature RBF lookup table: 2048 entries over [-2,2], (value, delta) for lerp.
__global__ void k_rbf_build(const float* __restrict__ wrbf, const float* __restrict__ mu,
                            const float* __restrict__ sigma){
  int fo = blockIdx.x;
  float sg = sigma[0];
  float inv2s2 = 0.5f/(sg*sg);
  float mu0 = mu[0];
  float dmu = mu[1] - mu0;
  const float lo = -2.f, h = 4.f/(float)(TABN - 1);
  float wloc[KR];
#pragma unroll 1
  for (int k = 0; k < KR; ++k) wloc[k] = wrbf[fo*KR + k];
  for (int j = threadIdx.x; j < TABN; j += 256){
    float u0 = lo + h*(float)j;
    float u1 = u0 + h;
    float s0 = 0.f, s1 = 0.f;
#pragma unroll 1
    for (int k = 0; k < KR; ++k){
      float m = fmaf((float)k, dmu, mu0);
      float d0 = u0 - m, d1 = u1 - m;
      s0 += wloc[k] * __expf(-d0*d0*inv2s2);
      s1 += wloc[k] * __expf(-d1*d1*inv2s2);
    }
    d_rbf_tab[fo*TABN + j] = make_float2(s0, s1 - s0);
  }
}

// conv(2->32, 11x11, pad 5) fused with LUT-RBF activation -> d_fuk
// block 16x16 threads, tile 64x16 px, 16 output feats per block (z parity)
__global__ void __launch_bounds__(256, 2) k_conv_rbf(const float* __restrict__ ck){
  __shared__ float4 sW[16*121];     // (wx,wx,wy,wy)
  __shared__ float  sIn[2*26*74];
  int tx = threadIdx.x, ty = threadIdx.y;
  int tid = ty*16 + tx;
  int z = blockIdx.z, n = z >> 1, fo0 = (z & 1)*16;
  for (int i = tid; i < 16*121; i += 256){
    int fo = i/121, tap = i - fo*121;
    float2 w = ((const float2*)ck)[(fo0+fo)*121 + tap];
    sW[i] = make_float4(w.x, w.x, w.y, w.y);
  }
  int y0 = blockIdx.y*16, x0 = blockIdx.x*64;
  for (int i = tid; i < 2*26*74; i += 256){
    int comp = i / (26*74), rem = i - comp*(26*74);
    int iy = rem/74, ix = rem - iy*74;
    int gy = y0 - 5 + iy, gx = x0 - 5 + ix;
    float v = 0.f;
    if (gy >= 0 && gy < HP && gx >= 0 && gx < HP)
      v = d_upad[((long)(n*2+comp)*HP + gy)*HP + gx];
    sIn[i] = v;
  }
  __syncthreads();

  ull acc[32];
#pragma unroll
  for (int i = 0; i < 32; ++i) acc[i] = 0ull;

  for (int ky = 0; ky < 11; ++ky){
#pragma unroll
    for (int kx = 0; kx < 11; ++kx){
      int ro = (ty+ky)*74 + tx + kx;
      float r0a = sIn[ro],      r0b = sIn[ro+16];
      float r1a = sIn[ro+32],   r1b = sIn[ro+48];
      float q0a = sIn[1924+ro],    q0b = sIn[1924+ro+16];
      float q1a = sIn[1924+ro+32], q1b = sIn[1924+ro+48];
      ull vr0, vr1, vi0, vi1;
      PACKF2(vr0, r0a, r0b); PACKF2(vr1, r1a, r1b);
      PACKF2(vi0, q0a, q0b); PACKF2(vi1, q1a, q1b);
      const ulonglong2* wp = reinterpret_cast<const ulonglong2*>(sW) + (ky*11 + kx);
#pragma unroll
      for (int fo = 0; fo < 16; ++fo){
        ulonglong2 w = wp[fo*121];
        FMAF2(acc[2*fo],   vr0, w.x, acc[2*fo]);
        FMAF2(acc[2*fo],   vi0, w.y, acc[2*fo]);
        FMAF2(acc[2*fo+1], vr1, w.x, acc[2*fo+1]);
        FMAF2(acc[2*fo+1], vi1, w.y, acc[2*fo+1]);
      }
    }
  }

  // LUT-RBF epilogue: clamp, scale, gather (value,delta), lerp
  const float lo = -2.f;
  const float invh = (float)(TABN - 1) / 4.f;
  int ybase = y0 + ty;
  bool yok = (ybase < HP);
  long obase = ((long)(n*NF + fo0)*HP + ybase)*HP + x0 + tx;
#pragma unroll 1
  for (int fo = 0; fo < 16; ++fo){
    const float2* tab = d_rbf_tab + (fo0 + fo)*TABN;
#pragma unroll
    for (int pr = 0; pr < 2; ++pr){
      float ulo, uhi;
      UNPACKF2(ulo, uhi, acc[2*fo+pr]);
#pragma unroll
      for (int hf = 0; hf < 2; ++hf){
        float uv = hf ? uhi : ulo;
        int xoff = pr*32 + hf*16;
        int gx = x0 + tx + xoff;
        if (yok && gx < HP){
          float t = (uv - lo) * invh;
          t = fminf(fmaxf(t, 0.f), (float)(TABN - 1) - 1.001f);
          int i = (int)t;
          float fr = t - (float)i;
          float2 e = __ldg(&tab[i]);
          d_fuk[obase + (long)fo*HP*HP + xoff] = fmaf(e.y, fr, e.x);
        }
      }
    }
  }
}

// ---------------- launcher ----------------
extern "C" void kernel_launch(void* const* d_in, const int* in_sizes, int n_in,
                              void* d_out, int out_size){
  const float* u     = (const float*)d_in[0];
  const float* f     = (const float*)d_in[1];
  const float* coil  = (const float*)d_in[2];
  const float* mask  = (const float*)d_in[3];
  const float* ck    = (const float*)d_in[4];
  const float* wrbf  = (const float*)d_in[5];
  const float* mu    = (const float*)d_in[6];
  const float* sigma = (const float*)d_in[7];
  const float* lamb  = (const float*)d_in[8];
  float2* out = (float2*)d_out;

  // regularizer front end
  k_rbf_build<<<NF, 256>>>(wrbf, mu, sigma);
  k_pad<<<(Nb*2*HP*HP + 255)/256, 256>>>(u);
  k_conv_rbf<<<dim3(6, 22, 8), dim3(16, 16)>>>(ck);

  // merged: convT (400 blocks) + dcA 16-line (1200 blocks)
  k_mix<<<CT_BLOCKS + Nb*Cc*20, 256>>>(ck, u, coil);

  // data-consistency tail
  k_dcB<<<Nb*Cc*40, 128>>>(f, mask);
  k_dcC<<<Nb*Hh, 256>>>(u, coil, lamb, out);
}

// round 15
// speedup vs baseline: 1.1575x; 1.0643x over previous
#include <cuda_runtime.h>

// ---------------- problem constants ----------------
#define Nb   4
#define Cc   15
#define Hh   320
#define Ww   320
#define PADR 11
#define HP   342          // H + 2*PADR
#define NF   32
#define KS   11
#define KR   31
#define IMG  (Hh*Ww)      // 102400
#define NCIMG (Nb*Cc*IMG) // 6144000
#define TABN 2048

typedef unsigned long long ull;

// packed f32x2 helpers (Blackwell)
#define PACKF2(d, lo, hi) asm("mov.b64 %0, {%1, %2};" : "=l"(d) : "f"(lo), "f"(hi))
#define UNPACKF2(lo, hi, v) asm("mov.b64 {%0, %1}, %2;" : "=f"(lo), "=f"(hi) : "l"(v))
#define FMAF2(d, a, b, c) asm("fma.rn.f32x2 %0, %1, %2, %3;" : "=l"(d) : "l"(a), "l"(b), "l"(c))
#define EX2F(d, x) asm("ex2.approx.ftz.f32 %0, %1;" : "=f"(d) : "f"(x))

// ---------------- device scratch ----------------
__device__ float2 d_ws1[NCIMG];
__device__ float2 d_ws2[NCIMG];
__device__ float  d_upad[Nb*2*HP*HP];
__device__ float  d_fuk[Nb*NF*HP*HP];
__device__ float2 d_ru[Nb*IMG];
__device__ float2 d_ru2[Nb*IMG];
__device__ float2 d_ru3[Nb*IMG];
__device__ float2 d_ru4[Nb*IMG];
__device__ float2 d_rbf_tab[NF*TABN];   // (value, delta-to-next) per entry

// ---------------- complex helpers ----------------
__device__ __forceinline__ float2 cadd(float2 a, float2 b){ return make_float2(a.x+b.x, a.y+b.y); }
__device__ __forceinline__ float2 csub(float2 a, float2 b){ return make_float2(a.x-b.x, a.y-b.y); }
__device__ __forceinline__ float2 cmul(float2 a, float2 b){ return make_float2(a.x*b.x-a.y*b.y, a.x*b.y+a.y*b.x); }

// ---------- 320-point in-place Stockham FFT (radix 4,4,4,5), 16 thr/line ----------
#define LINES 8
#define SMW   321

template<int NS>
__device__ __forceinline__ void r4ip(float2* A, int t, float dir){
  float2 v[5][4];
#pragma unroll
  for (int it = 0; it < 5; ++it){
    int j = t + (it << 4);
    v[it][0] = A[j]; v[it][1] = A[j+80]; v[it][2] = A[j+160]; v[it][3] = A[j+240];
  }
  __syncthreads();
#pragma unroll
  for (int it = 0; it < 5; ++it){
    int j    = t + (it << 4);
    int base = j & (NS - 1);
    int grp  = j / NS;
    float2 v0 = v[it][0], v1 = v[it][1], v2 = v[it][2], v3 = v[it][3];
    if (NS > 1){
      float ang = dir * (6.2831853071795864f / (4.0f*NS)) * (float)base;
      float s, c; __sincosf(ang, &s, &c);
      float2 w1 = make_float2(c, s);
      float2 w2 = cmul(w1, w1);
      float2 w3 = cmul(w2, w1);
      v1 = cmul(v1, w1); v2 = cmul(v2, w2); v3 = cmul(v3, w3);
    }
    float2 a0 = cadd(v0, v2), a1 = csub(v0, v2);
    float2 a2 = cadd(v1, v3), a3 = csub(v1, v3);
    float2 ja3 = make_float2(-dir*a3.y, dir*a3.x);
    int o = grp*(NS*4) + base;
    A[o]      = cadd(a0, a2);
    A[o+NS]   = cadd(a1, ja3);
    A[o+2*NS] = csub(a0, a2);
    A[o+3*NS] = csub(a1, ja3);
  }
  __syncthreads();
}

__device__ __forceinline__ void r5ip(float2* A, int t, float dir){
  const float C1 = 0.30901699437494745f, S1 = 0.9510565162951535f;
  const float C2 = -0.8090169943749473f, S2 = 0.5877852522924731f;
  float2 v[4][5];
#pragma unroll
  for (int it = 0; it < 4; ++it){
    int j = t + (it << 4);
    v[it][0]=A[j]; v[it][1]=A[j+64]; v[it][2]=A[j+128]; v[it][3]=A[j+192]; v[it][4]=A[j+256];
  }
  __syncthreads();
#pragma unroll
  for (int it = 0; it < 4; ++it){
    int j = t + (it << 4);
    float2 v0=v[it][0], v1=v[it][1], v2=v[it][2], v3=v[it][3], v4=v[it][4];
    float ang = dir * (6.2831853071795864f / 320.0f) * (float)j;
    float s, c; __sincosf(ang, &s, &c);
    float2 w1 = make_float2(c, s);
    float2 w2 = cmul(w1, w1);
    float2 w3 = cmul(w2, w1);
    float2 w4 = cmul(w2, w2);
    v1 = cmul(v1, w1); v2 = cmul(v2, w2); v3 = cmul(v3, w3); v4 = cmul(v4, w4);
    float2 t1 = cadd(v1, v4), t2 = cadd(v2, v3);
    float2 t3 = csub(v1, v4), t4 = csub(v2, v3);
    float2 X0 = cadd(v0, cadd(t1, t2));
    float2 m1 = make_float2(v0.x + C1*t1.x + C2*t2.x, v0.y + C1*t1.y + C2*t2.y);
    float2 m2 = make_float2(v0.x + C2*t1.x + C1*t2.x, v0.y + C2*t1.y + C1*t2.y);
    float2 s3 = make_float2(S1*t3.x + S2*t4.x, S1*t3.y + S2*t4.y);
    float2 s4 = make_float2(S2*t3.x - S1*t4.x, S2*t3.y - S1*t4.y);
    float2 js3 = make_float2(-dir*s3.y, dir*s3.x);
    float2 js4 = make_float2(-dir*s4.y, dir*s4.x);
    A[j]     = X0;
    A[j+64]  = cadd(m1, js3);
    A[j+128] = cadd(m2, js4);
    A[j+192] = csub(m2, js4);
    A[j+256] = csub(m1, js3);
  }
  __syncthreads();
}

__device__ __forceinline__ void fft320ip(float2* A, int t, float dir){
  r4ip<1>(A, t, dir);
  r4ip<4>(A, t, dir);
  r4ip<16>(A, t, dir);
  r5ip(A, t, dir);
}

// Pass A: sgn*u*coil -> row FFT (fwd) -> ws1
__global__ void __launch_bounds__(128, 8) k_dcA(const float* __restrict__ u, const float* __restrict__ coil){
  __shared__ float2 sA[LINES*SMW];
  int tid = threadIdx.x;
  int img = blockIdx.x / 40;
  int r0  = (blockIdx.x % 40) * 8;
  int n   = img / Cc;
  const float2* up = (const float2*)u + (long)n*IMG;
  const float2* cp = (const float2*)coil + (long)img*IMG;
  for (int idx = tid; idx < LINES*320; idx += 128){
    int l = idx / 320, p = idx - l*320;
    int r = r0 + l;
    float2 uv = up[(long)r*Ww + p];
    float2 cv = cp[(long)r*Ww + p];
    float sgn = ((r + p) & 1) ? -1.f : 1.f;
    sA[l*SMW + p] = make_float2(sgn*(uv.x*cv.x - uv.y*cv.y), sgn*(uv.x*cv.y + uv.y*cv.x));
  }
  __syncthreads();
  fft320ip(sA + (tid >> 4)*SMW, tid & 15, -1.f);
  float2* dp = d_ws1 + (long)img*IMG + (long)r0*Ww;
  for (int idx = tid; idx < LINES*320; idx += 128){
    int l = idx / 320, p = idx - l*320;
    dp[idx] = sA[l*SMW + p];
  }
}

// Pass B: col FFT fwd -> mask*(v/320 - sgn*f) -> col FFT inv -> ws2
__global__ void __launch_bounds__(128, 8) k_dcB(const float* __restrict__ f, const float* __restrict__ mask){
  __shared__ float2 sA[LINES*SMW];
  int tid = threadIdx.x;
  int img = blockIdx.x / 40;
  int c0  = (blockIdx.x % 40) * 8;
  int n   = img / Cc;
  const float2* sp = d_ws1 + (long)img*IMG + c0;
  for (int idx = tid; idx < LINES*320; idx += 128){
    int r = idx >> 3, cc = idx & 7;
    sA[cc*SMW + r] = sp[(long)r*Ww + cc];
  }
  __syncthreads();
  fft320ip(sA + (tid >> 4)*SMW, tid & 15, -1.f);
  const float2* fp = (const float2*)f + (long)img*IMG + c0;
  const float*  mp = mask + (long)n*IMG + c0;
  for (int idx = tid; idx < LINES*320; idx += 128){
    int r = idx >> 3, cc = idx & 7;
    float2 v = sA[cc*SMW + r];
    float2 fv = fp[(long)r*Ww + cc];
    float  mv = mp[(long)r*Ww + cc];
    float sgn = ((r + c0 + cc) & 1) ? -1.f : 1.f;
    v.x = mv*(v.x*(1.f/320.f) - sgn*fv.x);
    v.y = mv*(v.y*(1.f/320.f) - sgn*fv.y);
    sA[cc*SMW + r] = v;
  }
  __syncthreads();
  fft320ip(sA + (tid >> 4)*SMW, tid & 15, 1.f);
  float2* dp = d_ws2 + (long)img*IMG + c0;
  for (int idx = tid; idx < LINES*320; idx += 128){
    int r = idx >> 3, cc = idx & 7;
    dp[(long)r*Ww + cc] = sA[cc*SMW + r];
  }
}

// Pass C fused with final combine:
// block = (n, row). 16 lines: 15 coils' row r of ws2 + 1 dummy.
// row inverse FFT -> out = u - (Ru1+Ru2+Ru3+Ru4) - lamb*sgn*(1/320)*sum_c V_c*conj(coil_c)
__global__ void __launch_bounds__(256) k_dcC(const float* __restrict__ u,
                                             const float* __restrict__ coil,
                                             const float* __restrict__ lamb,
                                             float2* __restrict__ out){
  __shared__ float2 sA[16*SMW];
  int tid = threadIdx.x;
  int n = blockIdx.x / Hh;
  int r = blockIdx.x - n*Hh;
  for (int idx = tid; idx < 16*320; idx += 256){
    int line = idx / 320;
    int p = idx - line*320;
    float2 v = make_float2(0.f, 0.f);
    if (line < Cc)
      v = d_ws2[((long)(n*Cc + line))*IMG + (long)r*Ww + p];
    sA[line*SMW + p] = v;
  }
  __syncthreads();
  fft320ip(sA + (tid >> 4)*SMW, tid & 15, 1.f);
  float lam = lamb[0];
  for (int p = tid; p < 320; p += 256){
    float ax = 0.f, ay = 0.f;
#pragma unroll 1
    for (int c = 0; c < Cc; ++c){
      float2 wv = sA[c*SMW + p];
      float2 cc = ((const float2*)coil)[((long)(n*Cc + c))*IMG + (long)r*Ww + p];
      ax += wv.x*cc.x + wv.y*cc.y;
      ay += wv.y*cc.x - wv.x*cc.y;
    }
    float sgn = ((r + p) & 1) ? -1.f : 1.f;
    float s = lam * sgn * (1.f/320.f);
    long q = (long)n*IMG + (long)r*Ww + p;
    float2 uv = ((const float2*)u)[q];
    float2 r1 = d_ru[q];
    float2 r2 = d_ru2[q];
    float2 r3 = d_ru3[q];
    float2 r4 = d_ru4[q];
    float rx = (r1.x + r2.x) + (r3.x + r4.x);
    float ry = (r1.y + r2.y) + (r3.y + r4.y);
    out[q] = make_float2(uv.x - rx - s*ax, uv.y - ry - s*ay);
  }
}

// ---------------- regularizer path ----------------
__global__ void k_pad(const float* __restrict__ u){
  int idx = blockIdx.x*256 + threadIdx.x;
  const int total = Nb*2*HP*HP;
  if (idx >= total) return;
  int xx = idx % HP; int t1 = idx / HP;
  int yy = t1 % HP;  int t2 = t1 / HP;
  int comp = t2 & 1; int n = t2 >> 1;
  int p = yy - PADR; if (p < 0) p = -p; else if (p >= Hh) p = 2*Hh - 2 - p;
  int q = xx - PADR; if (q < 0) q = -q; else if (q >= Ww) q = 2*Ww - 2 - q;
  d_upad[idx] = u[(((long)n*Hh + p)*Ww + q)*2 + comp];
}

// Build per-feature RBF lookup table: 2048 entries over [-2,2], (value, delta) for lerp.
__global__ void k_rbf_build(const float* __restrict__ wrbf, const float* __restrict__ mu,
                            const float* __restrict__ sigma){
  int fo = blockIdx.x;
  float sg = sigma[0];
  float inv2s2 = 0.5f/(sg*sg);
  float mu0 = mu[0];
  float dmu = mu[1] - mu0;
  const float lo = -2.f, h = 4.f/(float)(TABN - 1);
  float wloc[KR];
#pragma unroll 1
  for (int k = 0; k < KR; ++k) wloc[k] = wrbf[fo*KR + k];
  for (int j = threadIdx.x; j < TABN; j += 256){
    float u0 = lo + h*(float)j;
    float u1 = u0 + h;
    float s0 = 0.f, s1 = 0.f;
#pragma unroll 1
    for (int k = 0; k < KR; ++k){
      float m = fmaf((float)k, dmu, mu0);
      float d0 = u0 - m, d1 = u1 - m;
      s0 += wloc[k] * __expf(-d0*d0*inv2s2);
      s1 += wloc[k] * __expf(-d1*d1*inv2s2);
    }
    d_rbf_tab[fo*TABN + j] = make_float2(s0, s1 - s0);
  }
}

// conv(2->32, 11x11, pad 5) fused with LUT-RBF activation -> d_fuk
// block 16x16 threads, tile 64x16 px, 16 output feats per block (z parity)
__global__ void __launch_bounds__(256, 2) k_conv_rbf(const float* __restrict__ ck){
  __shared__ float4 sW[16*121];     // (wx,wx,wy,wy)
  __shared__ float  sIn[2*26*74];
  int tx = threadIdx.x, ty = threadIdx.y;
  int tid = ty*16 + tx;
  int z = blockIdx.z, n = z >> 1, fo0 = (z & 1)*16;
  for (int i = tid; i < 16*121; i += 256){
    int fo = i/121, tap = i - fo*121;
    float2 w = ((const float2*)ck)[(fo0+fo)*121 + tap];
    sW[i] = make_float4(w.x, w.x, w.y, w.y);
  }
  int y0 = blockIdx.y*16, x0 = blockIdx.x*64;
  for (int i = tid; i < 2*26*74; i += 256){
    int comp = i / (26*74), rem = i - comp*(26*74);
    int iy = rem/74, ix = rem - iy*74;
    int gy = y0 - 5 + iy, gx = x0 - 5 + ix;
    float v = 0.f;
    if (gy >= 0 && gy < HP && gx >= 0 && gx < HP)
      v = d_upad[((long)(n*2+comp)*HP + gy)*HP + gx];
    sIn[i] = v;
  }
  __syncthreads();

  ull acc[32];
#pragma unroll
  for (int i = 0; i < 32; ++i) acc[i] = 0ull;

  for (int ky = 0; ky < 11; ++ky){
#pragma unroll
    for (int kx = 0; kx < 11; ++kx){
      int ro = (ty+ky)*74 + tx + kx;
      float r0a = sIn[ro],      r0b = sIn[ro+16];
      float r1a = sIn[ro+32],   r1b = sIn[ro+48];
      float q0a = sIn[1924+ro],    q0b = sIn[1924+ro+16];
      float q1a = sIn[1924+ro+32], q1b = sIn[1924+ro+48];
      ull vr0, vr1, vi0, vi1;
      PACKF2(vr0, r0a, r0b); PACKF2(vr1, r1a, r1b);
      PACKF2(vi0, q0a, q0b); PACKF2(vi1, q1a, q1b);
      const ulonglong2* wp = reinterpret_cast<const ulonglong2*>(sW) + (ky*11 + kx);
#pragma unroll
      for (int fo = 0; fo < 16; ++fo){
        ulonglong2 w = wp[fo*121];
        FMAF2(acc[2*fo],   vr0, w.x, acc[2*fo]);
        FMAF2(acc[2*fo],   vi0, w.y, acc[2*fo]);
        FMAF2(acc[2*fo+1], vr1, w.x, acc[2*fo+1]);
        FMAF2(acc[2*fo+1], vi1, w.y, acc[2*fo+1]);
      }
    }
  }

  // LUT-RBF epilogue: clamp, scale, gather (value,delta), lerp
  const float lo = -2.f;
  const float invh = (float)(TABN - 1) / 4.f;
  int ybase = y0 + ty;
  bool yok = (ybase < HP);
  long obase = ((long)(n*NF + fo0)*HP + ybase)*HP + x0 + tx;
#pragma unroll 1
  for (int fo = 0; fo < 16; ++fo){
    const float2* tab = d_rbf_tab + (fo0 + fo)*TABN;
#pragma unroll
    for (int pr = 0; pr < 2; ++pr){
      float ulo, uhi;
      UNPACKF2(ulo, uhi, acc[2*fo+pr]);
#pragma unroll
      for (int hf = 0; hf < 2; ++hf){
        float uv = hf ? uhi : ulo;
        int xoff = pr*32 + hf*16;
        int gx = x0 + tx + xoff;
        if (yok && gx < HP){
          float t = (uv - lo) * invh;
          t = fminf(fmaxf(t, 0.f), (float)(TABN - 1) - 1.001f);
          int i = (int)t;
          float fr = t - (float)i;
          float2 e = __ldg(&tab[i]);
          d_fuk[obase + (long)fo*HP*HP + xoff] = fmaf(e.y, fr, e.x);
        }
      }
    }
  }
}

// transposed conv (32->2), inner 320x320, /32
// block (8,32), tile 64x32 px, 8 px per thread; z = n*4 + quarter (8 channels each)
__global__ void __launch_bounds__(256) k_convT(const float* __restrict__ ck){
  __shared__ float  sIn[42*76];
  __shared__ float2 sW8[8*121];
  int tx = threadIdx.x;    // 0..7
  int ty = threadIdx.y;    // 0..31
  int tid = ty*8 + tx;
  int z = blockIdx.z;
  int n = z >> 2;
  int cbase = (z & 3)*8;
  int y0 = blockIdx.y*32, x0 = blockIdx.x*64;

  // preload this quarter's 8 channel weights
  for (int i = tid; i < 8*121; i += 256)
    sW8[i] = ((const float2*)ck)[(cbase + i/121)*121 + (i % 121)];

  ull acc[8];
#pragma unroll
  for (int i = 0; i < 8; ++i) acc[i] = 0ull;

#pragma unroll 1
  for (int ch = 0; ch < 8; ++ch){
    __syncthreads();
    {
      const float* src = d_fuk + (((long)(n*NF + cbase + ch))*HP + (y0 + 6))*HP + (x0 + 6);
      for (int i = tid; i < 42*74; i += 256){
        int iy = i/74, ix = i - iy*74;
        sIn[iy*76 + ix] = src[(long)iy*HP + ix];
      }
    }
    __syncthreads();
    const ull* wch = reinterpret_cast<const ull*>(sW8) + ch*121;
    for (int ly = 0; ly < 11; ++ly){
      const float* row = sIn + (ty + 10 - ly)*76 + tx*8;
      float4 va = *(const float4*)(row);
      float4 vb = *(const float4*)(row + 4);
      float4 vc = *(const float4*)(row + 8);
      float4 vd = *(const float4*)(row + 12);
      float4 ve = *(const float4*)(row + 16);
      float vv[18] = {va.x,va.y,va.z,va.w, vb.x,vb.y,vb.z,vb.w,
                      vc.x,vc.y,vc.z,vc.w, vd.x,vd.y,vd.z,vd.w,
                      ve.x,ve.y};
      ull vdup[18];
#pragma unroll
      for (int j = 0; j < 18; ++j) PACKF2(vdup[j], vv[j], vv[j]);
#pragma unroll
      for (int lx = 0; lx < 11; ++lx){
        ull wp = wch[ly*11 + lx];          // (wx, wy)
#pragma unroll
        for (int p = 0; p < 8; ++p){
          FMAF2(acc[p], vdup[p + 10 - lx], wp, acc[p]);
        }
      }
    }
  }
  float sc = 1.0f/NF;
  int qsel = z & 3;
  float2* dst = (qsel == 0) ? d_ru : (qsel == 1) ? d_ru2 : (qsel == 2) ? d_ru3 : d_ru4;
#pragma unroll
  for (int p = 0; p < 8; ++p){
    float ax, ay; UNPACKF2(ax, ay, acc[p]);
    dst[((long)n*Hh + (y0 + ty))*Ww + (x0 + tx*8 + p)] = make_float2(ax*sc, ay*sc);
  }
}

// ---------------- launcher ----------------
extern "C" void kernel_launch(void* const* d_in, const int* in_sizes, int n_in,
                              void* d_out, int out_size){
  const float* u     = (const float*)d_in[0];
  const float* f     = (const float*)d_in[1];
  const float* coil  = (const float*)d_in[2];
  const float* mask  = (const float*)d_in[3];
  const float* ck    = (const float*)d_in[4];
  const float* wrbf  = (const float*)d_in[5];
  const float* mu    = (const float*)d_in[6];
  const float* sigma = (const float*)d_in[7];
  const float* lamb  = (const float*)d_in[8];
  float2* out = (float2*)d_out;

  // regularizer path
  k_rbf_build<<<NF, 256>>>(wrbf, mu, sigma);
  k_pad<<<(Nb*2*HP*HP + 255)/256, 256>>>(u);
  k_conv_rbf<<<dim3(6, 22, 8), dim3(16, 16)>>>(ck);
  k_convT<<<dim3(5, 10, 16), dim3(8, 32)>>>(ck);

  // data-consistency path (fused)
  k_dcA<<<Nb*Cc*40, 128>>>(u, coil);
  k_dcB<<<Nb*Cc*40, 128>>>(f, mask);
  k_dcC<<<Nb*Hh, 256>>>(u, coil, lamb, out);
}